// round 17
// baseline (speedup 1.0000x reference)
#include <cuda_runtime.h>
#include <cstdint>
#include <math.h>

#define B_ 8
#define C_ 128
#define HW (256*256)
typedef unsigned long long ull;

// ----------------------------- device scratch -----------------------------
__device__ __align__(16) float g_actv[(size_t)B_*C_*HW];          // 268MB
__device__ __align__(16) float g_V[(size_t)36*B_*C_*4096];        // 604MB [k][b][ci][tile]
__device__ __align__(16) float g_M[(size_t)36*B_*C_*4096*2];      // 1.21GB [k][b][co][tile]{g,b}
__device__ __align__(16) float g_U2[36*C_*512];                   // [k][ci][n*2] duplicated
__device__ __align__(16) float g_Wp[19*16*128];                   // [j][slot][co]
__device__ float g_nT[(size_t)B_*HW];
__device__ float g_mean[B_*C_];
__device__ float g_rstd[B_*C_];
__device__ float g_mu[B_*20*64];
__device__ __align__(16) float g_G2[B_*20*9*C_*2];
__device__ __align__(16) float g_G4[B_*20*16*C_*2];
__device__ unsigned char g_cls[B_*128*128];
__device__ float g_Cg[C_], g_Cb[C_], g_scal[2];

// ----------------------------- helpers -----------------------------
__device__ __forceinline__ ull fma2(ull a, ull b, ull c) {
    ull d;
    asm("fma.rn.f32x2 %0, %1, %2, %3;" : "=l"(d) : "l"(a), "l"(b), "l"(c));
    return d;
}
__device__ __forceinline__ ull pack2(float x, float y) {
    ull d;
    asm("mov.b64 %0, {%1, %2};" : "=l"(d) : "f"(x), "f"(y));
    return d;
}
__device__ __forceinline__ uint32_t smem_u32(const void* p) {
    uint32_t a;
    asm("{ .reg .u64 t; cvta.to.shared.u64 t, %1; cvt.u32.u64 %0, t; }" : "=r"(a) : "l"(p));
    return a;
}
__device__ __forceinline__ void cpa16(uint32_t d, const void* g) {
    asm volatile("cp.async.ca.shared.global [%0], [%1], 16;" :: "r"(d), "l"(g) : "memory");
}
__device__ __forceinline__ void cp_commit() { asm volatile("cp.async.commit_group;" ::: "memory"); }
__device__ __forceinline__ void cp_wait0() { asm volatile("cp.async.wait_group 0;" ::: "memory"); }
__device__ __forceinline__ float2 f2add(float2 a, float2 b) { return make_float2(a.x + b.x, a.y + b.y); }
__device__ __forceinline__ float2 f2sub(float2 a, float2 b) { return make_float2(a.x - b.x, a.y - b.y); }
__device__ __forceinline__ float2 f2fma(float k, float2 a, float2 b) {
    return make_float2(fmaf(k, a.x, b.x), fmaf(k, a.y, b.y));
}

// ----------------------------- launch #1: merged prep -----------------------------
// [0] scal | [1,41) mu | [41,553) cls | [553,705) Wp | [705,833) U | [833,1345) ntr
__global__ __launch_bounds__(256) void k_prep(
    const float* bg, const float* bb, const float* cgb, const float* cbb,
    const float* sgb, const float* sbb, const float* sc, const float* fcw,
    const float* fcb, const float* segmap, const float* ssw,
    const float* sgw, const float* sbw, const float* noise) {
    __shared__ float tsh[32][33];
    int bk = blockIdx.x, tid = threadIdx.x;
    if (bk == 0) {
        if (tid < 128) {
            float ga = 1.f / (1.f + expf(-bg[0]));
            float ba = 1.f / (1.f + expf(-bb[0]));
            g_Cg[tid] = ga * cgb[tid] + (1.f - ga) * sgb[tid];
            g_Cb[tid] = ba * cbb[tid] + (1.f - ba) * sbb[tid];
            if (tid == 0) { g_scal[0] = ga; g_scal[1] = ba; }
        }
    } else if (bk < 41) {
        int bj = (bk - 1) * 4 + (tid >> 6), o = tid & 63;
        int b = bj / 20, j = bj - b * 20;
        float r = 0.f;
        if (j < 19) {
            const float* s = sc + (b * 19 + j) * 64;
            const float* w = fcw + (j * 64 + o) * 64;
            #pragma unroll 8
            for (int i = 0; i < 64; i++) r = fmaf(s[i], w[i], r);
            r = fmaxf(r + fcb[j * 64 + o], 0.f);
        }
        g_mu[bj * 64 + o] = r;
    } else if (bk < 553) {
        int idx = (bk - 41) * 256 + tid;
        int b = idx >> 14, p = idx & 16383;
        int cls = 19;
        for (int j = 18; j >= 0; j--)
            if (segmap[(((size_t)b * 19 + j) << 14) + p] > 0.f) { cls = j; break; }
        g_cls[idx] = (unsigned char)cls;
    } else if (bk < 705) {
        int idx = (bk - 553) * 256 + tid;       // 19*16*128 = 38912
        if (idx < 38912) {
            int j = idx >> 11, rem = idx & 2047;
            int slot = rem >> 7, co = rem & 127;
            int ph = slot >> 3, pw = (slot >> 2) & 1, u = (slot >> 1) & 1, v = slot & 1;
            int ylo = (ph == 0) ? (u ? 0 : -1) : (u ? 1 : -1);
            int yhi = (ph == 0) ? (u ? 1 : -1) : (u ? 1 : 0);
            int xlo = (pw == 0) ? (v ? 0 : -1) : (v ? 1 : -1);
            int xhi = (pw == 0) ? (v ? 1 : -1) : (v ? 1 : 0);
            float s = 0.f;
            for (int dy = ylo; dy <= yhi; dy++)
                for (int dx = xlo; dx <= xhi; dx++)
                    s += ssw[(co * 19 + j) * 9 + (dy + 1) * 3 + (dx + 1)];
            g_Wp[idx] = s;
        }
    } else if (bk < 833) {
        int idx = (bk - 705) * 256 + tid;   // 32768 = 128ci x 256n
        int ci = idx >> 8, n = idx & 255;
        int co = n >> 1, sel = n & 1;
        const float* w = sel ? sbw : sgw;
        float g[3][3];
        #pragma unroll
        for (int t = 0; t < 9; t++) g[t / 3][t % 3] = w[(co * 128 + ci) * 9 + t];
        float t6[6][3];
        #pragma unroll
        for (int c = 0; c < 3; c++) {
            t6[0][c] = 0.25f * g[0][c];
            t6[1][c] = -(g[0][c] + g[1][c] + g[2][c]) * (1.f / 6.f);
            t6[2][c] = (-g[0][c] + g[1][c] - g[2][c]) * (1.f / 6.f);
            t6[3][c] = g[0][c] * (1.f / 24.f) + g[1][c] * (1.f / 12.f) + g[2][c] * (1.f / 6.f);
            t6[4][c] = g[0][c] * (1.f / 24.f) - g[1][c] * (1.f / 12.f) + g[2][c] * (1.f / 6.f);
            t6[5][c] = g[2][c];
        }
        #pragma unroll
        for (int i = 0; i < 6; i++) {
            float a = t6[i][0], bb2 = t6[i][1], c2 = t6[i][2];
            float u6[6];
            u6[0] = 0.25f * a;
            u6[1] = -(a + bb2 + c2) * (1.f / 6.f);
            u6[2] = (-a + bb2 - c2) * (1.f / 6.f);
            u6[3] = a * (1.f / 24.f) + bb2 * (1.f / 12.f) + c2 * (1.f / 6.f);
            u6[4] = a * (1.f / 24.f) - bb2 * (1.f / 12.f) + c2 * (1.f / 6.f);
            u6[5] = c2;
            #pragma unroll
            for (int kk = 0; kk < 6; kk++) {
                int o = ((i * 6 + kk) * 128 + ci) * 512 + n * 2;
                g_U2[o] = u6[kk];
                g_U2[o + 1] = u6[kk];
            }
        }
    } else {
        int bl = bk - 833;
        int b = bl >> 6, rem = bl & 63;
        int w0 = (rem & 7) * 32, h0 = (rem >> 3) * 32;
        int tx = tid & 31, ty = tid >> 5;
        for (int i = 0; i < 32; i += 8)
            tsh[ty + i][tx] = noise[((size_t)b * 256 + w0 + ty + i) * 256 + h0 + tx];
        __syncthreads();
        for (int i = 0; i < 32; i += 8)
            g_nT[((size_t)b * 256 + h0 + ty + i) * 256 + w0 + tx] = tsh[tx][ty + i];
    }
}

// ----------------------------- launch #2: stats -----------------------------
__global__ __launch_bounds__(256) void k_stats(const float* x, const float* nvar) {
    int bc = blockIdx.x;
    int b = bc >> 7, c = bc & 127;
    float nv = nvar[c];
    const float* xb = x + (size_t)bc * HW;
    const float* nb = g_nT + (size_t)b * HW;
    float s = 0.f, q = 0.f;
    for (int i = threadIdx.x; i < HW; i += 256) {
        float v = xb[i] + nb[i] * nv;
        s += v; q = fmaf(v, v, q);
    }
    __shared__ float ss[8], sq[8];
    #pragma unroll
    for (int o = 16; o; o >>= 1) {
        s += __shfl_xor_sync(0xffffffffu, s, o);
        q += __shfl_xor_sync(0xffffffffu, q, o);
    }
    int wid = threadIdx.x >> 5, lane = threadIdx.x & 31;
    if (!lane) { ss[wid] = s; sq[wid] = q; }
    __syncthreads();
    if (threadIdx.x == 0) {
        float S = 0.f, Q = 0.f;
        #pragma unroll
        for (int k = 0; k < 8; k++) { S += ss[k]; Q += sq[k]; }
        float m = S * (1.f / HW);
        g_mean[bc] = m;
        g_rstd[bc] = rsqrtf(Q * (1.f / HW) - m * m + 1e-5f);
    }
}

// ----------------------------- LUTs -----------------------------
__global__ __launch_bounds__(128) void k_lut1(const float* gw, const float* bw) {
    int bj = blockIdx.x, co = threadIdx.x;
    __shared__ float mu_s[64];
    if (co < 64) mu_s[co] = g_mu[bj * 64 + co];
    __syncthreads();
    for (int t = 0; t < 9; t++) {
        float sg = 0.f, sb = 0.f;
        #pragma unroll 8
        for (int ci = 0; ci < 64; ci++) {
            float m = mu_s[ci];
            sg = fmaf(gw[(co * 64 + ci) * 9 + t], m, sg);
            sb = fmaf(bw[(co * 64 + ci) * 9 + t], m, sb);
        }
        int o = ((bj * 9 + t) * 128 + co) * 2;
        g_G2[o] = sg; g_G2[o + 1] = sb;
    }
}

__global__ __launch_bounds__(256) void k_lut2() {
    int bj = blockIdx.x, n = threadIdx.x;
    const float* G = g_G2 + (size_t)bj * 9 * 256;
    float* O = g_G4 + (size_t)bj * 16 * 256;
    for (int ph = 0; ph < 2; ph++)
    for (int pw = 0; pw < 2; pw++)
    for (int u = 0; u < 2; u++)
    for (int v = 0; v < 2; v++) {
        int rlo = (u == 0) ? 0 : (ph == 0 ? 1 : 2);
        int rhi = (u == 0) ? (ph == 0 ? 0 : 1) : 2;
        int clo = (v == 0) ? 0 : (pw == 0 ? 1 : 2);
        int chi = (v == 0) ? (pw == 0 ? 0 : 1) : 2;
        float s = 0.f;
        for (int dy = rlo; dy <= rhi; dy++)
            for (int dx = clo; dx <= chi; dx++)
                s += G[(dy * 3 + dx) * 256 + n];
        O[(((ph * 2 + pw) * 2 + u) * 2 + v) * 256 + n] = s;
    }
}

// ----------------------------- actv via parity LUT, 8 px/thread -----------------------
__global__ __launch_bounds__(256, 2) void k_actv(const float* segmap, const float* ssb) {
    __shared__ float Sh[19][6][10];
    __shared__ __align__(16) float Wb[2][16][128];
    uint32_t Wb_u = smem_u32(Wb);
    int b = blockIdx.z;
    int x0 = blockIdx.x * 16, y0 = blockIdx.y * 8;
    int tid = threadIdx.x;
    int tx = tid & 15, ty = tid >> 4;
    int r = ty >> 2, c = (ty & 3) * 4;

    int hb = (y0 >> 1) - 1, cbh = (x0 >> 1) - 1;
    for (int idx = tid; idx < 19 * 60; idx += 256) {
        int j = idx / 60, pos = idx - j * 60;
        int hr = pos / 10, hc = pos - hr * 10;
        int gy = hb + hr, gx = cbh + hc;
        float v = 0.f;
        if ((unsigned)gy < 128u && (unsigned)gx < 128u)
            v = segmap[(((size_t)b * 19 + j) << 14) + gy * 128 + gx];
        Sh[j][hr][hc] = v;
    }
    int ph = r & 1;
    int row0 = (r >> 1) + ph;
    int col0 = c >> 1;

    ull acc[2][4][4];
    #pragma unroll
    for (int g = 0; g < 2; g++)
        #pragma unroll
        for (int i = 0; i < 4; i++)
            #pragma unroll
            for (int q = 0; q < 4; q++) acc[g][i][q] = 0ull;

    auto issueW = [&](int j, int buf) {
        const float* src = g_Wp + j * 2048;
        #pragma unroll
        for (int k = 0; k < 2; k++) {
            int idx = tid * 2 + k;
            cpa16(Wb_u + (uint32_t)(buf * 2048 + idx * 4) * 4u, src + idx * 4);
        }
        cp_commit();
    };

    issueW(0, 0);
    #pragma unroll 1
    for (int j = 0; j < 19; j++) {
        cp_wait0();
        __syncthreads();
        if (j + 1 < 19) issueW(j + 1, (j + 1) & 1);
        int buf = j & 1;
        float Sv[2][2][4];
        #pragma unroll
        for (int g = 0; g < 2; g++)
            #pragma unroll
            for (int u = 0; u < 2; u++)
                #pragma unroll
                for (int v = 0; v < 4; v++)
                    Sv[g][u][v] = Sh[j][row0 + 2 * g + u][col0 + v];
        #pragma unroll
        for (int u = 0; u < 2; u++)
            #pragma unroll
            for (int v = 0; v < 2; v++) {
                ulonglong2 W0a = *(const ulonglong2*)&Wb[buf][((ph * 2 + 0) * 2 + u) * 2 + v][tx * 4];
                ulonglong2 W0b = *(const ulonglong2*)&Wb[buf][((ph * 2 + 0) * 2 + u) * 2 + v][tx * 4 + 64];
                ulonglong2 W1a = *(const ulonglong2*)&Wb[buf][((ph * 2 + 1) * 2 + u) * 2 + v][tx * 4];
                ulonglong2 W1b = *(const ulonglong2*)&Wb[buf][((ph * 2 + 1) * 2 + u) * 2 + v][tx * 4 + 64];
                #pragma unroll
                for (int i = 0; i < 4; i++) {
                    int pw = i & 1, cb2 = (i >> 1) + (i & 1);
                    const ulonglong2& Wa = pw ? W1a : W0a;
                    const ulonglong2& Wc = pw ? W1b : W0b;
                    #pragma unroll
                    for (int g = 0; g < 2; g++) {
                        float s = Sv[g][u][cb2 + v];
                        ull a = pack2(s, s);
                        acc[g][i][0] = fma2(a, Wa.x, acc[g][i][0]);
                        acc[g][i][1] = fma2(a, Wa.y, acc[g][i][1]);
                        acc[g][i][2] = fma2(a, Wc.x, acc[g][i][2]);
                        acc[g][i][3] = fma2(a, Wc.y, acc[g][i][3]);
                    }
                }
            }
        __syncthreads();
    }

    int xg0 = x0 + c;
    #pragma unroll
    for (int g = 0; g < 2; g++) {
        int y = y0 + r + 4 * g;
        #pragma unroll
        for (int q = 0; q < 4; q++) {
            int co0 = (q < 2) ? (tx * 4 + q * 2) : (tx * 4 + 64 + (q - 2) * 2);
            #pragma unroll
            for (int h2 = 0; h2 < 2; h2++) {
                int co = co0 + h2;
                float bias = ssb[co];
                float4 o;
                float* op = (float*)&o;
                #pragma unroll
                for (int p = 0; p < 4; p++) {
                    ull v = acc[g][p][q];
                    unsigned w32 = h2 ? (unsigned)(v >> 32) : (unsigned)v;
                    op[p] = fmaxf(__uint_as_float(w32) + bias, 0.f);
                }
                *(float4*)&g_actv[(((size_t)b * 128 + co) * 256 + y) * 256 + xg0] = o;
            }
        }
    }
}

// ----------------------------- F(4,3) input transform V = Bt d B -----------------------
__global__ __launch_bounds__(256) void k_vt() {
    __shared__ float sm[66][68];
    int tid = threadIdx.x;
    int ci = blockIdx.y, b = blockIdx.z;
    int ry = blockIdx.x >> 2, rx = blockIdx.x & 3;
    int y0 = ry * 64, x0 = rx * 64;
    const float* src = g_actv + ((size_t)b * 128 + ci) * HW;
    for (int idx = tid; idx < 66 * 66; idx += 256) {
        int r = idx / 66, c = idx - r * 66;
        int gy = y0 - 1 + r, gx = x0 - 1 + c;
        float v = 0.f;
        if ((unsigned)gy < 256u && (unsigned)gx < 256u) v = src[gy * 256 + gx];
        sm[r][c] = v;
    }
    __syncthreads();
    int ty = tid >> 4, tx = tid & 15;
    float t6[6][6];
    #pragma unroll
    for (int j = 0; j < 6; j++) {
        float d0 = sm[4 * ty + 0][4 * tx + j], d1 = sm[4 * ty + 1][4 * tx + j];
        float d2 = sm[4 * ty + 2][4 * tx + j], d3 = sm[4 * ty + 3][4 * tx + j];
        float d4 = sm[4 * ty + 4][4 * tx + j], d5 = sm[4 * ty + 5][4 * tx + j];
        t6[0][j] = 4.f * d0 - 5.f * d2 + d4;
        t6[1][j] = -4.f * (d1 + d2) + d3 + d4;
        t6[2][j] = 4.f * (d1 - d2) - d3 + d4;
        t6[3][j] = -2.f * d1 - d2 + 2.f * d3 + d4;
        t6[4][j] = 2.f * d1 - d2 - 2.f * d3 + d4;
        t6[5][j] = 4.f * d1 - 5.f * d3 + d5;
    }
    int gtile = (ry * 16 + ty) * 64 + rx * 16 + tx;
    float* dst = g_V + ((size_t)b * 128 + ci) * 4096 + gtile;
    const size_t ks = (size_t)8 * 128 * 4096;
    #pragma unroll
    for (int i = 0; i < 6; i++) {
        float s0 = t6[i][0], s1 = t6[i][1], s2 = t6[i][2];
        float s3 = t6[i][3], s4 = t6[i][4], s5 = t6[i][5];
        dst[(size_t)(i * 6 + 0) * ks] = 4.f * s0 - 5.f * s2 + s4;
        dst[(size_t)(i * 6 + 1) * ks] = -4.f * (s1 + s2) + s3 + s4;
        dst[(size_t)(i * 6 + 2) * ks] = 4.f * (s1 - s2) - s3 + s4;
        dst[(size_t)(i * 6 + 3) * ks] = -2.f * s1 - s2 + 2.f * s3 + s4;
        dst[(size_t)(i * 6 + 4) * ks] = 2.f * s1 - s2 - 2.f * s3 + s4;
        dst[(size_t)(i * 6 + 5) * ks] = 4.f * s1 - 5.f * s3 + s5;
    }
}

// ----------------------------- 36x batched GEMM -> fp32 M ---------------------------
// f32x2 lanes pair adjacent m-tiles; U pre-duplicated (g_U2) so no pack in inner loop.
// Warp owns 16 m (wid*16); lane owns 4 n-floats (lane*4..+3) = 2 (gamma,beta) co pairs.
__global__ __launch_bounds__(256, 2) void k_gemm() {
    __shared__ __align__(16) float As[2][16][128];
    __shared__ __align__(16) float Us[2][16][256];
    uint32_t As_u = smem_u32(As), Us_u = smem_u32(Us);
    int tid = threadIdx.x, lane = tid & 31, wid = tid >> 5;
    int mb = blockIdx.x;
    int k = blockIdx.y >> 1, nb = blockIdx.y & 1;
    int b = blockIdx.z;
    const float* Vb = g_V + ((size_t)(k * 8 + b) * 128) * 4096 + mb * 128;
    const float* Ub = g_U2 + (size_t)k * 128 * 512 + nb * 256;

    ull acc[8][4];
    #pragma unroll
    for (int p = 0; p < 8; p++)
        #pragma unroll
        for (int j = 0; j < 4; j++) acc[p][j] = 0ull;

    auto issue = [&](int c, int buf) {
        #pragma unroll
        for (int j = 0; j < 2; j++) {
            int idx = tid * 2 + j;              // 512 float4 for A
            int row = idx >> 5, col = (idx & 31) * 4;
            cpa16(As_u + (uint32_t)((buf * 16 + row) * 128 + col) * 4u,
                  Vb + (size_t)(c * 16 + row) * 4096 + col);
        }
        #pragma unroll
        for (int j = 0; j < 4; j++) {
            int idx = tid * 4 + j;              // 1024 float4 for U
            int row = idx >> 6, col = (idx & 63) * 4;
            cpa16(Us_u + (uint32_t)((buf * 16 + row) * 256 + col) * 4u,
                  Ub + (size_t)(c * 16 + row) * 512 + col);
        }
        cp_commit();
    };

    issue(0, 0);
    #pragma unroll 1
    for (int c = 0; c < 8; c++) {
        cp_wait0();
        __syncthreads();
        if (c + 1 < 8) issue(c + 1, (c + 1) & 1);
        int buf = c & 1;
        #pragma unroll
        for (int ci = 0; ci < 16; ci++) {
            const float* ar = &As[buf][ci][wid * 16];
            ulonglong2 a01 = *(const ulonglong2*)(ar);
            ulonglong2 a23 = *(const ulonglong2*)(ar + 4);
            ulonglong2 a45 = *(const ulonglong2*)(ar + 8);
            ulonglong2 a67 = *(const ulonglong2*)(ar + 12);
            const float* ur = &Us[buf][ci][lane * 8];
            ulonglong2 u01 = *(const ulonglong2*)(ur);
            ulonglong2 u23 = *(const ulonglong2*)(ur + 4);
            ull ap[8] = { a01.x, a01.y, a23.x, a23.y, a45.x, a45.y, a67.x, a67.y };
            ull ud[4] = { u01.x, u01.y, u23.x, u23.y };
            #pragma unroll
            for (int p = 0; p < 8; p++) {
                acc[p][0] = fma2(ap[p], ud[0], acc[p][0]);
                acc[p][1] = fma2(ap[p], ud[1], acc[p][1]);
                acc[p][2] = fma2(ap[p], ud[2], acc[p][2]);
                acc[p][3] = fma2(ap[p], ud[3], acc[p][3]);
            }
        }
        __syncthreads();
    }
    // store: transpose (m-pair, n) regs back to (gamma,beta)-per-tile layout
    #pragma unroll
    for (int c2 = 0; c2 < 2; c2++) {
        int co = nb * 64 + lane * 2 + c2;
        ull* Mr = (ull*)g_M + ((size_t)(k * 8 + b) * 128 + co) * 4096 + mb * 128 + wid * 16;
        #pragma unroll
        for (int p = 0; p < 8; p++) {
            ull g = acc[p][2 * c2];       // (gamma m0, gamma m1)
            ull bb = acc[p][2 * c2 + 1];  // (beta  m0, beta  m1)
            ulonglong2 s;
            s.x = (g & 0xffffffffull) | (bb << 32);
            s.y = (g >> 32) | (bb & 0xffffffff00000000ull);
            *(ulonglong2*)(Mr + 2 * p) = s;
        }
    }
}

// ----------------------------- inverse transform + fused epilogue -------------------
__global__ __launch_bounds__(256) void k_inv(const float* __restrict__ x,
                                             const float* __restrict__ nvar,
                                             float* __restrict__ out) {
    int tid = threadIdx.x;
    int b = blockIdx.z;
    int tile = blockIdx.x * 256 + tid;
    int ty = tile >> 6, tx = tile & 63;
    int co0 = blockIdx.y * 16;
    int y0 = 4 * ty, x0 = 4 * tx;

    int cls16[4][4];
    #pragma unroll
    for (int i = 0; i < 4; i++)
        #pragma unroll
        for (int j = 0; j < 4; j++) {
            int cy = 2 * ty - 1 + i, cx = 2 * tx - 1 + j;
            int cls = 19;
            if ((unsigned)cy < 128u && (unsigned)cx < 128u)
                cls = g_cls[((size_t)b << 14) + cy * 128 + cx];
            cls16[i][j] = cls;
        }
    float nz[4][4];
    #pragma unroll
    for (int rr = 0; rr < 4; rr++)
        *(float4*)nz[rr] = *(const float4*)&g_nT[((size_t)b * 256 + y0 + rr) * 256 + x0];
    float ga = g_scal[0], ba = g_scal[1];
    const size_t ks = (size_t)8 * 128 * 4096;
    const float c1t[6] = {0.f, 1.f, -1.f, 2.f, -2.f, 0.f};
    const float c2t[6] = {0.f, 1.f, 1.f, 4.f, 4.f, 0.f};
    const float c3t[6] = {0.f, 1.f, -1.f, 8.f, -8.f, 1.f};

    #pragma unroll 1
    for (int ic = 0; ic < 16; ic++) {
        int co = co0 + ic;
        const float2* Mp = (const float2*)g_M + ((size_t)b * 128 + co) * 4096 + tile;
        float2 Y[4][4];
        #pragma unroll
        for (int h = 0; h < 4; h++)
            #pragma unroll
            for (int w = 0; w < 4; w++) Y[h][w] = make_float2(0.f, 0.f);
        #pragma unroll
        for (int i = 0; i < 6; i++) {
            float2 m[6];
            #pragma unroll
            for (int j = 0; j < 6; j++) m[j] = Mp[(size_t)(i * 6 + j) * ks];
            float2 s12 = f2add(m[1], m[2]), d12 = f2sub(m[1], m[2]);
            float2 s34 = f2add(m[3], m[4]), d34 = f2sub(m[3], m[4]);
            float2 P[4];
            P[0] = f2add(f2add(m[0], s12), s34);
            P[1] = f2fma(2.f, d34, d12);
            P[2] = f2fma(4.f, s34, s12);
            P[3] = f2add(f2fma(8.f, d34, d12), m[5]);
            float a1 = c1t[i], a2 = c2t[i], a3 = c3t[i];
            #pragma unroll
            for (int w = 0; w < 4; w++) {
                if (i < 5) Y[0][w] = f2add(Y[0][w], P[w]);
                Y[1][w] = f2fma(a1, P[w], Y[1][w]);
                Y[2][w] = f2fma(a2, P[w], Y[2][w]);
                Y[3][w] = f2fma(a3, P[w], Y[3][w]);
            }
        }
        float mean = g_mean[b * 128 + co];
        float rs = g_rstd[b * 128 + co];
        float nv = nvar[co];
        float cg = g_Cg[co], cb = g_Cb[co];
        size_t base = (((size_t)b * 128 + co) * 256 + y0) * 256 + x0;
        #pragma unroll
        for (int h = 0; h < 4; h++) {
            float4 xv = *(const float4*)&x[base + h * 256];
            const float* xp = (const float*)&xv;
            float o4[4];
            int ph = h & 1;
            int cr = ((h - 1) >> 1) + 1;
            #pragma unroll
            for (int w = 0; w < 4; w++) {
                int pw = w & 1;
                int cc = ((w - 1) >> 1) + 1;
                float ag = 0.f, ab = 0.f;
                #pragma unroll
                for (int u = 0; u < 2; u++)
                    #pragma unroll
                    for (int v = 0; v < 2; v++) {
                        unsigned row = (unsigned)(((((b * 20 + cls16[cr + u][cc + v]) * 2 + ph) * 2 + pw) * 2 + u) * 2 + v) * 256u;
                        float2 gg = *(const float2*)&g_G4[row + (unsigned)co * 2u];
                        ag += gg.x; ab += gg.y;
                    }
                float gf = ga * ag + (1.f - ga) * Y[h][w].x + cg;
                float bf = ba * ab + (1.f - ba) * Y[h][w].y + cb;
                float val = (xp[w] + nz[h][w] * nv - mean) * rs;
                o4[w] = fmaf(val, gf, val + bf);
            }
            *(float4*)&out[base + h * 256] = make_float4(o4[0], o4[1], o4[2], o4[3]);
        }
    }
}

// ----------------------------- launch -----------------------------
extern "C" void kernel_launch(void* const* d_in, const int* in_sizes, int n_in,
                              void* d_out, int out_size) {
    const float* x     = (const float*)d_in[0];
    const float* seg   = (const float*)d_in[1];
    const float* sc    = (const float*)d_in[2];
    const float* noise = (const float*)d_in[3];
    const float* nvar  = (const float*)d_in[4];
    const float* bg    = (const float*)d_in[5];
    const float* bb    = (const float*)d_in[6];
    const float* fcw   = (const float*)d_in[7];
    const float* fcb   = (const float*)d_in[8];
    const float* cgw   = (const float*)d_in[9];
    const float* cbw   = (const float*)d_in[11];
    const float* ssw   = (const float*)d_in[13];
    const float* ssb   = (const float*)d_in[14];
    const float* sgw   = (const float*)d_in[15];
    const float* sbw   = (const float*)d_in[17];
    float* out = (float*)d_out;

    k_prep<<<1345, 256>>>(bg, bb, (const float*)d_in[10], (const float*)d_in[12],
                          (const float*)d_in[16], (const float*)d_in[18],
                          sc, fcw, fcb, seg, ssw, sgw, sbw, noise);
    k_stats<<<1024, 256>>>(x, nvar);
    k_lut1<<<160, 128>>>(cgw, cbw);
    k_actv<<<dim3(16, 32, 8), 256>>>(seg, ssb);
    k_vt<<<dim3(16, 128, 8), 256>>>();
    k_gemm<<<dim3(32, 72, 8), 256>>>();
    k_lut2<<<160, 256>>>();
    k_inv<<<dim3(16, 8, 8), 256>>>(x, nvar, out);
}